// round 13
// baseline (speedup 1.0000x reference)
#include <cuda_runtime.h>

typedef unsigned long long u64;

// ---- packed f32x2 helpers (sm_103a) ----
__device__ __forceinline__ u64 fma2(u64 a, u64 b, u64 c) {
    u64 d;
    asm("fma.rn.f32x2 %0, %1, %2, %3;" : "=l"(d) : "l"(a), "l"(b), "l"(c));
    return d;
}
__device__ __forceinline__ u64 mul2(u64 a, u64 b) {
    u64 d;
    asm("mul.rn.f32x2 %0, %1, %2;" : "=l"(d) : "l"(a), "l"(b));
    return d;
}
__device__ __forceinline__ u64 add2(u64 a, u64 b) {
    u64 d;
    asm("add.rn.f32x2 %0, %1, %2;" : "=l"(d) : "l"(a), "l"(b));
    return d;
}
__device__ __forceinline__ u64 relu2(u64 v) {
    unsigned a, b;
    asm("mov.b64 {%0, %1}, %2;" : "=r"(a), "=r"(b) : "l"(v));
    float lo = fmaxf(__uint_as_float(a), 0.0f);
    float hi = fmaxf(__uint_as_float(b), 0.0f);
    u64 d;
    asm("mov.b64 %0, {%1, %2};" : "=l"(d) : "r"(__float_as_uint(lo)), "r"(__float_as_uint(hi)));
    return d;
}
__device__ __forceinline__ u64 lds64(unsigned a) {
    u64 v;
    asm volatile("ld.shared.b64 %0, [%1];" : "=l"(v) : "r"(a));
    return v;
}

// ---- problem constants ----
constexpr int W_DIM = 4096;
constexpr int C_DIM = 64;
constexpr int L_SEG = 256;              // outputs per segment
constexpr int SEGS  = W_DIM / L_SEG;    // 16
constexpr int BH    = 16 * 21;          // 336 rows
constexpr int N_SEG_TOTAL = BH * SEGS;  // 5376 segments
constexpr int WU_IT = 2;                // warmup iterations (64 steps)
constexpr int N_IT  = (64 + L_SEG) / 32;              // 10 iterations
constexpr int DEPTH = 3;                // cp.async pipeline depth (blocks)
constexpr int BLK_BYTES = 32 * 256;     // 32 positions x 256 B = 8 KB
constexpr int WARP_SMEM = DEPTH * BLK_BYTES;          // 24 KB per 1-warp block
constexpr int GRID = 148 * 8;           // 1184 persistent 1-warp blocks (1 wave)

// Cross-correlation, zero pad. pad_lo: d=1 -> 3, d=2 -> 7, d=4 -> 14.
// y1[w] = relu(sum_k x [w- 3+  k] * w1[k])
// y2[w] = relu(sum_k y1[w- 7+ 2k] * w2[k])   (y1 := 0 outside [0,W))
// y3[w] = relu(sum_k y2[w-14+ 4k] * w3[k])   (y2 := 0 outside [0,W))
//
// Proven schedule (R12, 163 us): per warp, lane = 2 packed channels, t0=s0-36.
// smem blk b holds positions t0+8+32b .. t0+39+32b (8 KB, gmem-contiguous).
// step i (iter k = i/32, u = i&31):
//   LDS    x pos t0+i+8 from blk k, offs u  -> xr[(u+8)&15]  (8-step lead)
//   STAGE1 y1 @ t0+i-4   -> y1r[u&15]     (x slots i-7..i)
//   STAGE2 y2 @ t0+i-12  -> y2r[u&31]     (y1 steps i-15..i-1, 1-step lag)
//   STAGE3 y3 @ t0+i-28  -> STG           (y2 steps i-30..i-2, 2-step lag)
// cp.async zero-fills OOB positions (src_size=0) -> no gmem branches.
// MUST stay at 255-reg budget: lower budgets demote y2r[32] to local mem.
//
// R13 change (inner loop byte-identical): persistent grid of 1184 one-warp
// blocks (exactly 1 wave: 148 SM x 8 resident) pulling segment ids from a
// global atomic counter. Removes the ~10% static-assignment tail (640 of
// 1184 slots ran 5 segments instead of 4.54 avg). 1 ATOMG per 320-step
// segment = noise. Counter reset by a tiny kernel each launch (graph-safe).

__device__ unsigned g_seg_ctr;

__global__ void reset_ctr_kernel() { g_seg_ctr = 0u; }

__device__ __forceinline__ void prefetch_blk(const char* gsrc, int p0,
                                             unsigned sdst, int lane)
{
    #pragma unroll
    for (int j = 0; j < 16; ++j) {
        const int idx = j * 32 + lane;           // 16B chunk index in the 8KB blk
        const int p   = p0 + (idx >> 4);         // position this chunk belongs to
        const unsigned ok = (p >= 0 && p < W_DIM) ? 16u : 0u;
        asm volatile("cp.async.cg.shared.global [%0], [%1], 16, %2;"
                     :: "r"(sdst + idx * 16), "l"(gsrc + idx * 16), "r"(ok)
                     : "memory");
    }
    asm volatile("cp.async.commit_group;" ::: "memory");
}

#define LDS_STEP(u)                                                            \
    {                                                                          \
        xr[((u) + 8) & 15] = lds64(cons + (u) * 256);                          \
    }

#define STAGE1(u)                                                              \
    {                                                                          \
        u64 a0 = mul2(xr[((u) - 7) & 15], w1r[0]);                             \
        u64 a1 = mul2(xr[((u) - 6) & 15], w1r[1]);                             \
        a0 = fma2(xr[((u) - 5) & 15], w1r[2], a0);                             \
        a1 = fma2(xr[((u) - 4) & 15], w1r[3], a1);                             \
        a0 = fma2(xr[((u) - 3) & 15], w1r[4], a0);                             \
        a1 = fma2(xr[((u) - 2) & 15], w1r[5], a1);                             \
        a0 = fma2(xr[((u) - 1) & 15], w1r[6], a0);                             \
        a1 = fma2(xr[((u) - 0) & 15], w1r[7], a1);                             \
        u64 y1v = relu2(add2(a0, a1));                                         \
        if (BOUNDARY) {                                                        \
            const int p1 = pb + (u) - 4;                                       \
            if (p1 < 0 || p1 >= W_DIM) y1v = 0ull;                             \
        }                                                                      \
        y1r[(u) & 15] = y1v;                                                   \
    }

#define STAGE2(u)                                                              \
    {                                                                          \
        u64 b0 = mul2(y1r[((u) - 15) & 15], w2r[0]);                           \
        u64 b1 = mul2(y1r[((u) - 13) & 15], w2r[1]);                           \
        b0 = fma2(y1r[((u) - 11) & 15], w2r[2], b0);                           \
        b1 = fma2(y1r[((u) -  9) & 15], w2r[3], b1);                           \
        b0 = fma2(y1r[((u) -  7) & 15], w2r[4], b0);                           \
        b1 = fma2(y1r[((u) -  5) & 15], w2r[5], b1);                           \
        b0 = fma2(y1r[((u) -  3) & 15], w2r[6], b0);                           \
        b1 = fma2(y1r[((u) -  1) & 15], w2r[7], b1);                           \
        u64 y2v = relu2(add2(b0, b1));                                         \
        if (BOUNDARY) {                                                        \
            const int p2 = pb + (u) - 12;                                      \
            if (p2 < 0 || p2 >= W_DIM) y2v = 0ull;                             \
        }                                                                      \
        y2r[(u) & 31] = y2v;                                                   \
    }

#define STAGE3_STORE(u)                                                        \
    {                                                                          \
        u64 c0 = mul2(y2r[((u) - 30) & 31], w3r[0]);                           \
        u64 c1 = mul2(y2r[((u) - 26) & 31], w3r[1]);                           \
        c0 = fma2(y2r[((u) - 22) & 31], w3r[2], c0);                           \
        c1 = fma2(y2r[((u) - 18) & 31], w3r[3], c1);                           \
        c0 = fma2(y2r[((u) - 14) & 31], w3r[4], c0);                           \
        c1 = fma2(y2r[((u) - 10) & 31], w3r[5], c1);                           \
        c0 = fma2(y2r[((u) -  6) & 31], w3r[6], c0);                           \
        c1 = fma2(y2r[((u) -  2) & 31], w3r[7], c1);                           \
        const u64 y3v = relu2(add2(c0, c1));                                   \
        __stcs((u64*)(sp + (u) * C_DIM), y3v);                                 \
    }

template<bool BOUNDARY>
__device__ __forceinline__ void run_seg(
    const float* __restrict__ x,
    const u64* w1r, const u64* w2r, const u64* w3r,
    float* __restrict__ out,
    int bh, int seg, int lane, unsigned wsm)
{
    const int s0 = seg * L_SEG;
    const int t0 = s0 - 36;

    // prefetch stream: blk b = positions t0+8+32b .. t0+39+32b (8KB contiguous)
    const char* gpf = (const char*)x
                    + ((long long)bh * W_DIM + (t0 + 8)) * (C_DIM * 4);
    int ppf = t0 + 8;

    #pragma unroll
    for (int b = 0; b < DEPTH; ++b) {
        prefetch_blk(gpf, ppf, wsm + b * BLK_BYTES, lane);
        gpf += BLK_BYTES;
        ppf += 32;
    }

    float* sp = out + ((long long)bh * W_DIM + s0) * C_DIM + 2 * lane;
    int pb = t0;                                 // position of step at u=0

    u64 xr[16], y1r[16], y2r[32];
    #pragma unroll
    for (int j = 0; j < 16; ++j) xr[j]  = 0ull;
    #pragma unroll
    for (int j = 0; j < 16; ++j) y1r[j] = 0ull;
    #pragma unroll
    for (int j = 0; j < 32; ++j) y2r[j] = 0ull;

    unsigned cons = wsm + 2 * lane * 4;          // slot 0 base + lane offset
    const unsigned cons_hi = wsm + DEPTH * BLK_BYTES;

    for (int k = 0; k < N_IT; ++k) {
        // Need only blk k complete. Steady state with DEPTH=3: wait_group 2.
        if      (k >= N_IT - 1) asm volatile("cp.async.wait_group 0;" ::: "memory");
        else if (k == N_IT - 2) asm volatile("cp.async.wait_group 1;" ::: "memory");
        else                    asm volatile("cp.async.wait_group 2;" ::: "memory");
        __syncwarp();

        if (k == 0) {
            // y1 needed from step 17 on; y2 of steps 0..31 never read.
            #pragma unroll
            for (int u = 0; u < 32; ++u) {
                LDS_STEP(u) STAGE1(u)
            }
        } else if (k < WU_IT) {
            #pragma unroll
            for (int u = 0; u < 32; ++u) {
                LDS_STEP(u) STAGE1(u) STAGE2(u)
            }
        } else {
            #pragma unroll
            for (int u = 0; u < 32; ++u) {
                LDS_STEP(u) STAGE1(u) STAGE2(u) STAGE3_STORE(u)
            }
            sp += 32 * C_DIM;
        }

        // refill just-consumed slot with blk k+DEPTH
        if (k + DEPTH < N_IT) {
            prefetch_blk(gpf, ppf, cons - 2 * lane * 4, lane);
            gpf += BLK_BYTES;
            ppf += 32;
        }

        cons += BLK_BYTES;
        if (cons >= cons_hi) cons -= DEPTH * BLK_BYTES;
        pb += 32;
    }
}

__global__ void __launch_bounds__(32)
conv_stack_kernel(const float* __restrict__ x,
                  const float* __restrict__ w1,
                  const float* __restrict__ w2,
                  const float* __restrict__ w3,
                  float* __restrict__ out)
{
    extern __shared__ char smem[];

    const int lane = threadIdx.x & 31;
    const unsigned wsm = (unsigned)__cvta_generic_to_shared(smem);

    u64 w1r[8], w2r[8], w3r[8];
    #pragma unroll
    for (int k = 0; k < 8; ++k) {
        w1r[k] = *(const u64*)(w1 + k * C_DIM + 2 * lane);
        w2r[k] = *(const u64*)(w2 + k * C_DIM + 2 * lane);
        w3r[k] = *(const u64*)(w3 + k * C_DIM + 2 * lane);
    }

    // persistent work loop: pull segment ids until exhausted
    for (;;) {
        unsigned s;
        if (lane == 0) s = atomicAdd(&g_seg_ctr, 1u);
        s = __shfl_sync(0xFFFFFFFFu, s, 0);
        if (s >= (unsigned)N_SEG_TOTAL) break;

        const int bh  = (int)(s >> 4);       // s / SEGS
        const int seg = (int)(s & 15);       // s % SEGS

        if (seg == 0 || seg == SEGS - 1) {
            run_seg<true >(x, w1r, w2r, w3r, out, bh, seg, lane, wsm);
        } else {
            run_seg<false>(x, w1r, w2r, w3r, out, bh, seg, lane, wsm);
        }
    }
}

extern "C" void kernel_launch(void* const* d_in, const int* in_sizes, int n_in,
                              void* d_out, int out_size)
{
    const float* x  = (const float*)d_in[0];
    const float* w1 = (const float*)d_in[1];
    const float* w2 = (const float*)d_in[2];
    const float* w3 = (const float*)d_in[3];
    float* out = (float*)d_out;

    (void)in_sizes; (void)n_in; (void)out_size;

    cudaFuncSetAttribute(conv_stack_kernel,
                         cudaFuncAttributeMaxDynamicSharedMemorySize, WARP_SMEM);

    reset_ctr_kernel<<<1, 1>>>();
    conv_stack_kernel<<<GRID, 32, WARP_SMEM>>>(x, w1, w2, w3, out);
}